// round 2
// baseline (speedup 1.0000x reference)
#include <cuda_runtime.h>

// CapsuleLayer dynamic routing — priors fully register-resident.
// x: [B=256, N=1152, CI=8] f32, w: [C=10, N=1152, CI=8, CO=16] f32
// out: [C, B, 1, 1, 16] f32
//
// One CTA = (c, pair of b). 576 threads = 2 groups of 288 (one per b).
// Each thread owns NPT=4 route nodes; their 4x16 prior vectors live in
// registers for the whole kernel. Routing iterations are register FMA +
// warp shuffles + tiny 9-warp SMEM reductions. No large SMEM arrays.

#define Cc   10
#define Bb   256
#define Nn   1152
#define COo  16
#define Gg   2
#define GROUP 288          // threads per b-group (9 warps, multiple of 32)
#define NPT   4            // route nodes per thread: 288*4 = 1152
#define NTHREADS (Gg*GROUP)
#define NWG   9            // warps per group

__global__ __launch_bounds__(NTHREADS, 1)
void capsule_routing_kernel(const float* __restrict__ x,
                            const float* __restrict__ w,
                            float* __restrict__ out)
{
    __shared__ float wred[Gg*NWG*16];
    __shared__ float sred[Gg*NWG];
    __shared__ float outv[Gg*16];

    const int tid  = threadIdx.x;
    const int g    = tid / GROUP;           // which b of the pair
    const int r    = tid % GROUP;           // 0..287
    const int lane = r & 31;
    const int wg   = r >> 5;                // warp within group, 0..8
    const int c    = blockIdx.x / (Bb/Gg);
    const int b    = (blockIdx.x % (Bb/Gg)) * Gg + g;

    // ---------------- Phase 1: priors -> registers ----------------
    float P[NPT][16];
    #pragma unroll
    for (int k = 0; k < NPT; ++k) {
        const int n = r + k*GROUP;
        const float* xp = x + (b*Nn + n)*8;
        float4 xa = *(const float4*)(xp);
        float4 xb = *(const float4*)(xp + 4);
        float xi[8] = {xa.x, xa.y, xa.z, xa.w, xb.x, xb.y, xb.z, xb.w};

        const float* wp = w + ((long)c*Nn + n)*128;
        #pragma unroll
        for (int o = 0; o < 16; ++o) P[k][o] = 0.f;

        #pragma unroll
        for (int i = 0; i < 8; ++i) {
            const float xv = xi[i];
            float4 w0 = *(const float4*)(wp + i*16 + 0);
            float4 w1 = *(const float4*)(wp + i*16 + 4);
            float4 w2 = *(const float4*)(wp + i*16 + 8);
            float4 w3 = *(const float4*)(wp + i*16 + 12);
            P[k][0]  = fmaf(xv, w0.x, P[k][0]);
            P[k][1]  = fmaf(xv, w0.y, P[k][1]);
            P[k][2]  = fmaf(xv, w0.z, P[k][2]);
            P[k][3]  = fmaf(xv, w0.w, P[k][3]);
            P[k][4]  = fmaf(xv, w1.x, P[k][4]);
            P[k][5]  = fmaf(xv, w1.y, P[k][5]);
            P[k][6]  = fmaf(xv, w1.z, P[k][6]);
            P[k][7]  = fmaf(xv, w1.w, P[k][7]);
            P[k][8]  = fmaf(xv, w2.x, P[k][8]);
            P[k][9]  = fmaf(xv, w2.y, P[k][9]);
            P[k][10] = fmaf(xv, w2.z, P[k][10]);
            P[k][11] = fmaf(xv, w2.w, P[k][11]);
            P[k][12] = fmaf(xv, w3.x, P[k][12]);
            P[k][13] = fmaf(xv, w3.y, P[k][13]);
            P[k][14] = fmaf(xv, w3.z, P[k][14]);
            P[k][15] = fmaf(xv, w3.w, P[k][15]);
        }
    }

    // ---------------- Phase 2: routing (registers + shuffles) ----------------
    float Lr[NPT];   // per-thread logits, persist across iterations

    // --- iteration 0: uniform probs -> s = mean_n priors ---
    {
        float acc[16];
        #pragma unroll
        for (int o = 0; o < 16; ++o)
            acc[o] = P[0][o] + P[1][o] + P[2][o] + P[3][o];
        #pragma unroll
        for (int off = 16; off >= 1; off >>= 1)
            #pragma unroll
            for (int o = 0; o < 16; ++o)
                acc[o] += __shfl_xor_sync(0xffffffffu, acc[o], off);
        if (lane == 0) {
            #pragma unroll
            for (int o = 0; o < 16; ++o) wred[(g*NWG + wg)*16 + o] = acc[o];
        }
        __syncthreads();
        if (wg == 0) {
            float sv = 0.f;
            if (lane < 16) {
                #pragma unroll
                for (int wi = 0; wi < NWG; ++wi) sv += wred[(g*NWG + wi)*16 + lane];
                sv *= (1.0f / Nn);
            }
            float sq = (lane < 16) ? sv*sv : 0.f;
            #pragma unroll
            for (int off = 16; off >= 1; off >>= 1)
                sq += __shfl_xor_sync(0xffffffffu, sq, off);
            const float coef = sq / (1.f + sq) * rsqrtf(sq);
            if (lane < 16) outv[g*16 + lane] = sv * coef;
        }
        __syncthreads();
    }

    // --- iterations 1 and 2 ---
    #pragma unroll
    for (int it = 1; it < 3; ++it) {
        float ovr[16];
        #pragma unroll
        for (int o = 0; o < 16; ++o) ovr[o] = outv[g*16 + o];

        // logits update + local max (all registers)
        float lmax = -1e30f;
        #pragma unroll
        for (int k = 0; k < NPT; ++k) {
            float dot = 0.f;
            #pragma unroll
            for (int o = 0; o < 16; ++o) dot = fmaf(P[k][o], ovr[o], dot);
            const float L = (it == 1) ? dot : (Lr[k] + dot);
            Lr[k] = L;
            lmax  = fmaxf(lmax, L);
        }
        #pragma unroll
        for (int off = 16; off >= 1; off >>= 1)
            lmax = fmaxf(lmax, __shfl_xor_sync(0xffffffffu, lmax, off));
        __syncthreads();                    // sred free for reuse
        if (lane == 0) sred[g*NWG + wg] = lmax;
        __syncthreads();
        float M = -1e30f;
        #pragma unroll
        for (int wi = 0; wi < NWG; ++wi) M = fmaxf(M, sred[g*NWG + wi]);

        // exp + Z (registers)
        float e[NPT];
        float lsum = 0.f;
        #pragma unroll
        for (int k = 0; k < NPT; ++k) {
            e[k] = __expf(Lr[k] - M);
            lsum += e[k];
        }
        #pragma unroll
        for (int off = 16; off >= 1; off >>= 1)
            lsum += __shfl_xor_sync(0xffffffffu, lsum, off);
        __syncthreads();                    // all M reads done
        if (lane == 0) sred[g*NWG + wg] = lsum;
        __syncthreads();
        float Z = 0.f;
        #pragma unroll
        for (int wi = 0; wi < NWG; ++wi) Z += sred[g*NWG + wi];

        // weighted column sum: s[o] = (1/Z) * sum_n e[n]*P[n][o]
        float acc[16];
        #pragma unroll
        for (int o = 0; o < 16; ++o) {
            acc[o] = fmaf(e[0], P[0][o],
                     fmaf(e[1], P[1][o],
                     fmaf(e[2], P[2][o], e[3]*P[3][o])));
        }
        #pragma unroll
        for (int off = 16; off >= 1; off >>= 1)
            #pragma unroll
            for (int o = 0; o < 16; ++o)
                acc[o] += __shfl_xor_sync(0xffffffffu, acc[o], off);
        if (lane == 0) {
            #pragma unroll
            for (int o = 0; o < 16; ++o) wred[(g*NWG + wg)*16 + o] = acc[o];
        }
        __syncthreads();
        if (wg == 0) {
            float sv = 0.f;
            if (lane < 16) {
                #pragma unroll
                for (int wi = 0; wi < NWG; ++wi) sv += wred[(g*NWG + wi)*16 + lane];
                sv /= Z;
            }
            float sq = (lane < 16) ? sv*sv : 0.f;
            #pragma unroll
            for (int off = 16; off >= 1; off >>= 1)
                sq += __shfl_xor_sync(0xffffffffu, sq, off);
            const float coef = sq / (1.f + sq) * rsqrtf(sq);
            if (lane < 16) outv[g*16 + lane] = sv * coef;
        }
        __syncthreads();
    }

    // ---------------- output: [C, B, 1, 1, 16] ----------------
    if (r < 16) {
        out[(c*Bb + b)*16 + r] = outv[g*16 + r];
    }
}

extern "C" void kernel_launch(void* const* d_in, const int* in_sizes, int n_in,
                              void* d_out, int out_size)
{
    const float* x = (const float*)d_in[0];
    const float* w = (const float*)d_in[1];
    float* out = (float*)d_out;

    const int grid = Cc * (Bb / Gg);   // 1280 CTAs
    capsule_routing_kernel<<<grid, NTHREADS>>>(x, w, out);
}

// round 3
// speedup vs baseline: 2.9005x; 2.9005x over previous
#include <cuda_runtime.h>

// CapsuleLayer dynamic routing.
// x: [B=256, N=1152, CI=8] f32, w: [C=10, N=1152, CI=8, CO=16] f32
// out: [C, B, 1, 1, 16] f32
//
// One CTA = (c, pair of b). 576 threads. g = tid&1 (which b), r = tid>>1.
// Phase 1: 4 super-blocks of 288 w-rows; each block is staged GMEM->SMEM with
// coalesced LDG.128 + conflict-free STS (row stride 132 floats), then each
// thread reads its row from SMEM (lane pairs share a row -> 2-phase LDS.128)
// and accumulates its 16 priors in registers. P[4][16] stays register
// resident through all 3 routing iterations (phase 2 = shuffles + tiny SMEM).

#define Cc 10
#define Bb 256
#define Nn 1152
#define NTHREADS 576
#define NWARPS 18
#define NBLK 4
#define RPB 288            // rows per super-block
#define WS_STRIDE 33       // float4 per padded row (132 floats)
#define WS_F4 (RPB * WS_STRIDE)

#define SMEM_BYTES (WS_F4*16 + NWARPS*2*16*4 + NWARPS*2*4 + 2*16*4)

__global__ __launch_bounds__(NTHREADS, 1)
void capsule_kernel(const float* __restrict__ x,
                    const float* __restrict__ w,
                    float* __restrict__ out)
{
    extern __shared__ float4 smem4[];
    float4* ws   = smem4;                          // staged w block
    float*  wred = (float*)(ws + WS_F4);           // [18][2][16]
    float*  sred = wred + NWARPS*2*16;             // [18][2]
    float*  outv = sred + NWARPS*2;                // [2][16]

    const int tid  = threadIdx.x;
    const int g    = tid & 1;
    const int r    = tid >> 1;          // 0..287
    const int lane = tid & 31;
    const int wid  = tid >> 5;          // 0..17
    const int c    = blockIdx.x >> 7;            // /128
    const int b    = ((blockIdx.x & 127) << 1) + g;

    float P[NBLK][16];

    const float4* __restrict__ wsrc =
        (const float4*)(w + ((size_t)c * Nn) * 128);

    // ================= Phase 1: priors -> registers =================
    #pragma unroll
    for (int s = 0; s < NBLK; ++s) {
        if (s) __syncthreads();          // ws reuse guard
        // stage 288 rows (147 KB), coalesced
        #pragma unroll 4
        for (int m = tid; m < RPB * 32; m += NTHREADS) {
            const int row = m >> 5, q = m & 31;
            ws[row * WS_STRIDE + q] = wsrc[s * RPB * 32 + m];
        }
        __syncthreads();

        const int n = s * RPB + r;
        const float* xp = x + ((size_t)b * Nn + n) * 8;
        float4 xa = *(const float4*)xp;
        float4 xb = *(const float4*)(xp + 4);
        const float xv[8] = {xa.x, xa.y, xa.z, xa.w, xb.x, xb.y, xb.z, xb.w};

        #pragma unroll
        for (int o = 0; o < 16; ++o) P[s][o] = 0.f;

        const float4* wr = ws + r * WS_STRIDE;
        #pragma unroll
        for (int i = 0; i < 8; ++i) {
            const float xvi = xv[i];
            #pragma unroll
            for (int m = 0; m < 4; ++m) {
                const float4 wv = wr[i * 4 + m];
                P[s][4*m+0] = fmaf(xvi, wv.x, P[s][4*m+0]);
                P[s][4*m+1] = fmaf(xvi, wv.y, P[s][4*m+1]);
                P[s][4*m+2] = fmaf(xvi, wv.z, P[s][4*m+2]);
                P[s][4*m+3] = fmaf(xvi, wv.w, P[s][4*m+3]);
            }
        }
    }

    // ================= Phase 2: routing =================
    // warp reductions over same-g lanes: shfl_xor offsets 2,4,8,16
    float Lr[NBLK];

    // ---- iteration 0: s = mean_n priors ----
    {
        float acc[16];
        #pragma unroll
        for (int o = 0; o < 16; ++o)
            acc[o] = P[0][o] + P[1][o] + P[2][o] + P[3][o];
        #pragma unroll
        for (int off = 2; off <= 16; off <<= 1)
            #pragma unroll
            for (int o = 0; o < 16; ++o)
                acc[o] += __shfl_xor_sync(0xffffffffu, acc[o], off);
        __syncthreads();
        if (lane < 2) {
            #pragma unroll
            for (int o = 0; o < 16; ++o)
                wred[(wid * 2 + g) * 16 + o] = acc[o];
        }
        __syncthreads();
        if (tid < 32) {
            const int g2 = tid & 1, o2 = tid >> 1;
            float sv = 0.f;
            #pragma unroll
            for (int wi = 0; wi < NWARPS; ++wi)
                sv += wred[(wi * 2 + g2) * 16 + o2];
            sv *= (1.0f / Nn);
            float sq = sv * sv;
            #pragma unroll
            for (int off = 2; off <= 16; off <<= 1)
                sq += __shfl_xor_sync(0xffffffffu, sq, off);
            const float coef = sq / (1.f + sq) * rsqrtf(sq);
            outv[g2 * 16 + o2] = sv * coef;
        }
        __syncthreads();
    }

    // ---- iterations 1 and 2 ----
    #pragma unroll
    for (int it = 1; it < 3; ++it) {
        float ovr[16];
        #pragma unroll
        for (int o = 0; o < 16; ++o) ovr[o] = outv[g * 16 + o];

        // logits + max
        float lmax = -1e30f;
        #pragma unroll
        for (int k = 0; k < NBLK; ++k) {
            float dot = 0.f;
            #pragma unroll
            for (int o = 0; o < 16; ++o) dot = fmaf(P[k][o], ovr[o], dot);
            const float L = (it == 1) ? dot : (Lr[k] + dot);
            Lr[k] = L;
            lmax = fmaxf(lmax, L);
        }
        #pragma unroll
        for (int off = 2; off <= 16; off <<= 1)
            lmax = fmaxf(lmax, __shfl_xor_sync(0xffffffffu, lmax, off));
        __syncthreads();                 // prior consumers of sred done
        if (lane < 2) sred[wid * 2 + g] = lmax;
        __syncthreads();
        float M = -1e30f;
        #pragma unroll
        for (int wi = 0; wi < NWARPS; ++wi)
            M = fmaxf(M, sred[wi * 2 + g]);

        // exp + Z
        float e[NBLK], lsum = 0.f;
        #pragma unroll
        for (int k = 0; k < NBLK; ++k) {
            e[k] = __expf(Lr[k] - M);
            lsum += e[k];
        }
        #pragma unroll
        for (int off = 2; off <= 16; off <<= 1)
            lsum += __shfl_xor_sync(0xffffffffu, lsum, off);
        __syncthreads();                 // all M reads done
        if (lane < 2) sred[wid * 2 + g] = lsum;
        __syncthreads();
        float Z = 0.f;
        #pragma unroll
        for (int wi = 0; wi < NWARPS; ++wi)
            Z += sred[wi * 2 + g];

        // s[o] = (1/Z) * sum_n e[n] * P[n][o]
        float acc[16];
        #pragma unroll
        for (int o = 0; o < 16; ++o)
            acc[o] = fmaf(e[0], P[0][o],
                     fmaf(e[1], P[1][o],
                     fmaf(e[2], P[2][o], e[3] * P[3][o])));
        #pragma unroll
        for (int off = 2; off <= 16; off <<= 1)
            #pragma unroll
            for (int o = 0; o < 16; ++o)
                acc[o] += __shfl_xor_sync(0xffffffffu, acc[o], off);
        if (lane < 2) {
            #pragma unroll
            for (int o = 0; o < 16; ++o)
                wred[(wid * 2 + g) * 16 + o] = acc[o];
        }
        __syncthreads();
        if (tid < 32) {
            const int g2 = tid & 1, o2 = tid >> 1;
            float sv = 0.f;
            #pragma unroll
            for (int wi = 0; wi < NWARPS; ++wi)
                sv += wred[(wi * 2 + g2) * 16 + o2];
            sv /= Z;
            float sq = sv * sv;
            #pragma unroll
            for (int off = 2; off <= 16; off <<= 1)
                sq += __shfl_xor_sync(0xffffffffu, sq, off);
            const float coef = sq / (1.f + sq) * rsqrtf(sq);
            outv[g2 * 16 + o2] = sv * coef;
        }
        __syncthreads();
    }

    // ================= output: [C, B, 1, 1, 16] =================
    if (tid < 32) {
        const int g2 = tid & 1, o2 = tid >> 1;
        out[((size_t)c * Bb + ((blockIdx.x & 127) << 1) + g2) * 16 + o2] =
            outv[g2 * 16 + o2];
    }
}

extern "C" void kernel_launch(void* const* d_in, const int* in_sizes, int n_in,
                              void* d_out, int out_size)
{
    const float* x = (const float*)d_in[0];
    const float* w = (const float*)d_in[1];
    float* out = (float*)d_out;

    cudaFuncSetAttribute(capsule_kernel,
                         cudaFuncAttributeMaxDynamicSharedMemorySize, SMEM_BYTES);

    const int grid = Cc * (Bb / 2);   // 1280 CTAs
    capsule_kernel<<<grid, NTHREADS, SMEM_BYTES>>>(x, w, out);
}